// round 6
// baseline (speedup 1.0000x reference)
#include <cuda_runtime.h>
#include <cuda_fp16.h>
#include <cstdint>

// ---------------- problem constants ----------------
namespace {
constexpr int kE = 512, kF = 2048, kQ = 8;
constexpr int kRows = 16384;

constexpr int BM = 64, BN = 512, BK = 64;
constexpr int NTHR = 512;                 // 16 warps: 2 (m) x 8 (n)
constexpr int NCHUNK = kF / BK;           // 32
constexpr int NCTA = kRows / BM;          // 256

// SMEM layout (bytes)
constexpr int SM_B = 0;                   // 3 stages x (512 rows x 128B) = 196608
constexpr int SM_A = 196608;              // 2 stages x (64 rows x 128B)  = 16384
constexpr int SM_Z = 212992;              // z f32 [64][8] = 2048
constexpr int SM_TOTAL = 215040;
}

__device__ __align__(16) __half g_w2h[kE * kF];   // fp16 w2
__device__ __align__(16) float  g_w1t[kQ * kF];   // w1 transposed [q][f]

// ---------------- helpers ----------------
__device__ __forceinline__ uint32_t smem_u32(const void* p) {
    uint32_t a;
    asm("{ .reg .u64 t; cvta.to.shared.u64 t, %1; cvt.u32.u64 %0, t; }" : "=r"(a) : "l"(p));
    return a;
}
__device__ __forceinline__ uint32_t sw128(uint32_t off) { return off ^ ((off >> 3) & 0x70); }

__device__ __forceinline__ void cp_async16(uint32_t dst, const void* src) {
    asm volatile("cp.async.cg.shared.global [%0], [%1], 16;" :: "r"(dst), "l"(src) : "memory");
}
__device__ __forceinline__ void cp_commit() {
    asm volatile("cp.async.commit_group;" ::: "memory");
}
__device__ __forceinline__ void cp_wait1() {
    asm volatile("cp.async.wait_group 1;" ::: "memory");
}

__device__ __forceinline__ void ldsm4(uint32_t* r, uint32_t addr) {
    asm volatile("ldmatrix.sync.aligned.m8n8.x4.shared.b16 {%0,%1,%2,%3}, [%4];"
        : "=r"(r[0]), "=r"(r[1]), "=r"(r[2]), "=r"(r[3]) : "r"(addr));
}
__device__ __forceinline__ void mma16816(float* d, const uint32_t* a, const uint32_t* b) {
    asm volatile(
        "mma.sync.aligned.m16n8k16.row.col.f32.f16.f16.f32 "
        "{%0,%1,%2,%3}, {%4,%5,%6,%7}, {%8,%9}, {%0,%1,%2,%3};"
        : "+f"(d[0]), "+f"(d[1]), "+f"(d[2]), "+f"(d[3])
        : "r"(a[0]), "r"(a[1]), "r"(a[2]), "r"(a[3]), "r"(b[0]), "r"(b[1]));
}

// ---------------- prep kernels ----------------
__global__ void ffq_convert_w2(const float* __restrict__ w2) {
    int i = blockIdx.x * blockDim.x + threadIdx.x;
    float4 v = __ldg(reinterpret_cast<const float4*>(w2) + i);
    __half2* dst = reinterpret_cast<__half2*>(g_w2h);
    dst[2 * i]     = __floats2half2_rn(v.x, v.y);
    dst[2 * i + 1] = __floats2half2_rn(v.z, v.w);
}
__global__ void ffq_prep_w1(const float* __restrict__ w1) {
    int f = blockIdx.x * blockDim.x + threadIdx.x;   // 2048 threads
    const float4* p = reinterpret_cast<const float4*>(w1 + (size_t)f * kQ);
    float4 a = __ldg(p), b = __ldg(p + 1);
    g_w1t[0 * kF + f] = a.x; g_w1t[1 * kF + f] = a.y;
    g_w1t[2 * kF + f] = a.z; g_w1t[3 * kF + f] = a.w;
    g_w1t[4 * kF + f] = b.x; g_w1t[5 * kF + f] = b.y;
    g_w1t[6 * kF + f] = b.z; g_w1t[7 * kF + f] = b.w;
}

// ---------------- fused main kernel ----------------
__global__ void __launch_bounds__(NTHR, 1)
ffq_main(const float* __restrict__ x, const float* __restrict__ ry,
         const float* __restrict__ b1, const float* __restrict__ b2,
         float* __restrict__ out) {
    extern __shared__ char smem[];
    const uint32_t sb = smem_u32(smem);
    const int tid  = threadIdx.x;
    const int lane = tid & 31;
    const int wid  = tid >> 5;
    const int wm   = wid >> 3;          // 0..1
    const int wn   = wid & 7;           // 0..7
    const int m0   = blockIdx.x * BM;

    // act role: row r = tid>>3 (0..63), f-group cg = tid&7 (8 halfs)
    const int ar = tid >> 3;
    const int cg = tid & 7;

    // ---- prologue ----
    if (tid < BM) {  // z[row][q] = cos(x)*cos(ry) into smem
        const float4* xp = reinterpret_cast<const float4*>(x + (size_t)(m0 + tid) * kE);
        float4 a = __ldg(xp), b = __ldg(xp + 1);
        float xs[8] = {a.x, a.y, a.z, a.w, b.x, b.y, b.z, b.w};
        float* zs = reinterpret_cast<float*>(smem + SM_Z) + tid * 8;
#pragma unroll
        for (int q = 0; q < 8; q++) zs[q] = cosf(xs[q]) * cosf(__ldg(ry + q));
    }

    // B fill: w2 chunk [512 rows x 64 fp16]; thread = one e-row (8 x 16B)
    auto fill_B = [&](int st, int c) {
        const __half* src = g_w2h + (size_t)tid * kF + c * BK;
        const uint32_t dst = sb + SM_B + st * 65536;
        const uint32_t rowoff = (uint32_t)tid * 128;
#pragma unroll
        for (int j = 0; j < 8; j++)
            cp_async16(dst + sw128(rowoff + j * 16), src + j * 8);
    };
    fill_B(0, 0); cp_commit();
    fill_B(1, 1); cp_commit();
    __syncthreads();   // zs visible

    // z regs for my act row
    float zq[8];
    {
        const float4* zp = reinterpret_cast<const float4*>(smem + SM_Z + ar * 32);
        float4 z0 = zp[0], z1 = zp[1];
        zq[0] = z0.x; zq[1] = z0.y; zq[2] = z0.z; zq[3] = z0.w;
        zq[4] = z1.x; zq[5] = z1.y; zq[6] = z1.z; zq[7] = z1.w;
    }

    // act for chunk cc -> one 16B store into A[cc&1]
    auto act_chunk = [&](int cc) {
        const int f0 = cc * BK + cg * 8;
        float4 h0 = __ldg(reinterpret_cast<const float4*>(b1 + f0));
        float4 h1 = __ldg(reinterpret_cast<const float4*>(b1 + f0 + 4));
#pragma unroll
        for (int q = 0; q < 8; q++) {
            const float4 wa = __ldg(reinterpret_cast<const float4*>(g_w1t + q * kF + f0));
            const float4 wb = __ldg(reinterpret_cast<const float4*>(g_w1t + q * kF + f0 + 4));
            const float z = zq[q];
            h0.x = fmaf(z, wa.x, h0.x); h0.y = fmaf(z, wa.y, h0.y);
            h0.z = fmaf(z, wa.z, h0.z); h0.w = fmaf(z, wa.w, h0.w);
            h1.x = fmaf(z, wb.x, h1.x); h1.y = fmaf(z, wb.y, h1.y);
            h1.z = fmaf(z, wb.z, h1.z); h1.w = fmaf(z, wb.w, h1.w);
        }
        __half2 p0 = __floats2half2_rn(fmaxf(h0.x, 0.f), fmaxf(h0.y, 0.f));
        __half2 p1 = __floats2half2_rn(fmaxf(h0.z, 0.f), fmaxf(h0.w, 0.f));
        __half2 p2 = __floats2half2_rn(fmaxf(h1.x, 0.f), fmaxf(h1.y, 0.f));
        __half2 p3 = __floats2half2_rn(fmaxf(h1.z, 0.f), fmaxf(h1.w, 0.f));
        uint4 pk;
        pk.x = *reinterpret_cast<uint32_t*>(&p0);
        pk.y = *reinterpret_cast<uint32_t*>(&p1);
        pk.z = *reinterpret_cast<uint32_t*>(&p2);
        pk.w = *reinterpret_cast<uint32_t*>(&p3);
        *reinterpret_cast<uint4*>(smem + SM_A + (cc & 1) * 8192 +
                                  sw128((uint32_t)(ar * 128 + cg * 16))) = pk;
    };
    act_chunk(0);   // A[0] (stores become visible at iter-0 barrier)

    float acc[2][8][4];
#pragma unroll
    for (int mi = 0; mi < 2; mi++)
#pragma unroll
        for (int ni = 0; ni < 8; ni++)
#pragma unroll
            for (int j = 0; j < 4; j++) acc[mi][ni][j] = 0.f;

    // ---- main loop ----
#pragma unroll 1
    for (int c = 0; c < NCHUNK; c++) {
        cp_wait1();
        __syncthreads();             // B[c] ready; A[c&1] stores visible
        if (c + 2 < NCHUNK) fill_B((c + 2) % 3, c + 2);
        cp_commit();

        if (c + 1 < NCHUNK) act_chunk(c + 1);   // FFMA block — interleaves with MMA below

        const uint32_t Ab = sb + SM_A + (c & 1) * 8192;
        const uint32_t Bb = sb + SM_B + (c % 3) * 65536;
#pragma unroll
        for (int kc = 0; kc < 4; kc++) {
            uint32_t a[2][4];
#pragma unroll
            for (int mi = 0; mi < 2; mi++) {
                uint32_t row = wm * 32 + mi * 16 + (lane & 15);
                uint32_t col = kc * 32 + (lane >> 4) * 16;
                ldsm4(a[mi], Ab + sw128(row * 128 + col));
            }
            uint32_t b[4][4];
#pragma unroll
            for (int np = 0; np < 4; np++) {
                uint32_t row = wn * 64 + np * 16 + ((lane >> 4) & 1) * 8 + (lane & 7);
                uint32_t col = kc * 32 + ((lane >> 3) & 1) * 16;
                ldsm4(b[np], Bb + sw128(row * 128 + col));
            }
#pragma unroll
            for (int mi = 0; mi < 2; mi++)
#pragma unroll
                for (int ni = 0; ni < 8; ni++) {
                    uint32_t bf[2] = {b[ni >> 1][(ni & 1) * 2], b[ni >> 1][(ni & 1) * 2 + 1]};
                    mma16816(acc[mi][ni], a[mi], bf);
                }
        }
    }

    // ---- epilogue: += b2, store ----
#pragma unroll
    for (int ni = 0; ni < 8; ni++) {
        const int colp = wn * 64 + ni * 8 + (lane & 3) * 2;
        const float2 bv = __ldg(reinterpret_cast<const float2*>(b2 + colp));
#pragma unroll
        for (int mi = 0; mi < 2; mi++) {
            const int row0 = m0 + wm * 32 + mi * 16 + (lane >> 2);
            float2 v0 = make_float2(acc[mi][ni][0] + bv.x, acc[mi][ni][1] + bv.y);
            float2 v1 = make_float2(acc[mi][ni][2] + bv.x, acc[mi][ni][3] + bv.y);
            *reinterpret_cast<float2*>(out + (size_t)row0 * kE + colp) = v0;
            *reinterpret_cast<float2*>(out + (size_t)(row0 + 8) * kE + colp) = v1;
        }
    }
}

// ---------------- launch ----------------
extern "C" void kernel_launch(void* const* d_in, const int* in_sizes, int n_in,
                              void* d_out, int out_size) {
    (void)in_sizes; (void)n_in; (void)out_size;
    const float* x  = (const float*)d_in[0];
    const float* ry = (const float*)d_in[1];
    const float* w1 = (const float*)d_in[2];
    const float* b1 = (const float*)d_in[3];
    const float* w2 = (const float*)d_in[4];
    const float* b2 = (const float*)d_in[5];
    float* out = (float*)d_out;

    ffq_convert_w2<<<1024, 256>>>(w2);
    ffq_prep_w1<<<8, 256>>>(w1);

    cudaFuncSetAttribute(ffq_main, cudaFuncAttributeMaxDynamicSharedMemorySize, SM_TOTAL);
    ffq_main<<<NCTA, NTHR, SM_TOTAL>>>(x, ry, b1, b2, out);
}

// round 7
// speedup vs baseline: 2.2456x; 2.2456x over previous
#include <cuda_runtime.h>
#include <cuda_fp16.h>
#include <cstdint>

// ---------------- problem constants ----------------
namespace {
constexpr int kE = 512, kF = 2048, kQ = 8;
constexpr int kRows = 16384;

// GEMM tiling: 2 CTAs/SM
constexpr int BM = 128, BN = 128, BK = 64, STAGES = 3;
constexpr int GTHR = 256;                          // 8 warps: 2 (m) x 4 (n), warp tile 64x32
constexpr int STAGE_BYTES = BM * 128 + BN * 128;   // A 16KB + B 16KB = 32KB
constexpr int GSMEM = STAGES * STAGE_BYTES;        // 96KB
constexpr int NCHUNK = kF / BK;                    // 32

// act kernel
constexpr int ATHR = 256;
constexpr int AROWS = 64;
constexpr int ASM_W1 = 0;                          // f32 [8][2048] = 64KB
constexpr int ASM_B1 = 65536;                      // f32 [2048] = 8KB
constexpr int ASM_Z  = 73728;                      // f32 [64][8] = 2KB
constexpr int ASMEM  = 75776;
}

__device__ __align__(16) __half g_w2h[kE * kF];            // fp16 w2
__device__ __align__(16) __half g_act[(size_t)kRows * kF]; // fp16 relu(fc1), 64MB

// ---------------- helpers ----------------
__device__ __forceinline__ uint32_t smem_u32(const void* p) {
    uint32_t a;
    asm("{ .reg .u64 t; cvta.to.shared.u64 t, %1; cvt.u32.u64 %0, t; }" : "=r"(a) : "l"(p));
    return a;
}
__device__ __forceinline__ uint32_t sw128(uint32_t off) { return off ^ ((off >> 3) & 0x70); }

__device__ __forceinline__ void cp_async16(uint32_t dst, const void* src) {
    asm volatile("cp.async.cg.shared.global [%0], [%1], 16;" :: "r"(dst), "l"(src) : "memory");
}
__device__ __forceinline__ void cp_commit() {
    asm volatile("cp.async.commit_group;" ::: "memory");
}
__device__ __forceinline__ void cp_wait1() {
    asm volatile("cp.async.wait_group 1;" ::: "memory");
}

__device__ __forceinline__ void ldsm4(uint32_t* r, uint32_t addr) {
    asm volatile("ldmatrix.sync.aligned.m8n8.x4.shared.b16 {%0,%1,%2,%3}, [%4];"
        : "=r"(r[0]), "=r"(r[1]), "=r"(r[2]), "=r"(r[3]) : "r"(addr));
}
__device__ __forceinline__ void mma16816(float* d, const uint32_t* a, const uint32_t* b) {
    asm volatile(
        "mma.sync.aligned.m16n8k16.row.col.f32.f16.f16.f32 "
        "{%0,%1,%2,%3}, {%4,%5,%6,%7}, {%8,%9}, {%0,%1,%2,%3};"
        : "+f"(d[0]), "+f"(d[1]), "+f"(d[2]), "+f"(d[3])
        : "r"(a[0]), "r"(a[1]), "r"(a[2]), "r"(a[3]), "r"(b[0]), "r"(b[1]));
}

// ---------------- kernel 1: w2 -> fp16 ----------------
__global__ void ffq_convert_w2(const float* __restrict__ w2) {
    int i = blockIdx.x * blockDim.x + threadIdx.x;
    float4 v = __ldg(reinterpret_cast<const float4*>(w2) + i);
    __half2* dst = reinterpret_cast<__half2*>(g_w2h);
    dst[2 * i]     = __floats2half2_rn(v.x, v.y);
    dst[2 * i + 1] = __floats2half2_rn(v.z, v.w);
}

// ---------------- kernel 2: fused quantum + fc1 + relu -> fp16 act ----------------
__global__ void __launch_bounds__(ATHR, 2)
ffq_act(const float* __restrict__ x, const float* __restrict__ ry,
        const float* __restrict__ w1, const float* __restrict__ b1) {
    extern __shared__ char smem[];
    float* w1t = reinterpret_cast<float*>(smem + ASM_W1);  // [q][f]
    float* b1s = reinterpret_cast<float*>(smem + ASM_B1);
    float* zs  = reinterpret_cast<float*>(smem + ASM_Z);   // [row][q]
    const int tid = threadIdx.x;

    {   // stage w1 transposed: thread covers f = tid*8 .. +7
        const int f = tid * 8;
#pragma unroll
        for (int j = 0; j < 8; j++) {
            const float4* p = reinterpret_cast<const float4*>(w1 + (size_t)(f + j) * kQ);
            float4 a = __ldg(p), b = __ldg(p + 1);
            w1t[0 * kF + f + j] = a.x; w1t[1 * kF + f + j] = a.y;
            w1t[2 * kF + f + j] = a.z; w1t[3 * kF + f + j] = a.w;
            w1t[4 * kF + f + j] = b.x; w1t[5 * kF + f + j] = b.y;
            w1t[6 * kF + f + j] = b.z; w1t[7 * kF + f + j] = b.w;
        }
        *reinterpret_cast<float4*>(b1s + f)     = __ldg(reinterpret_cast<const float4*>(b1 + f));
        *reinterpret_cast<float4*>(b1s + f + 4) = __ldg(reinterpret_cast<const float4*>(b1 + f + 4));
    }
    if (tid < AROWS) {
        const float4* xp =
            reinterpret_cast<const float4*>(x + (size_t)(blockIdx.x * AROWS + tid) * kE);
        float4 a = __ldg(xp), b = __ldg(xp + 1);
        float xs[8] = {a.x, a.y, a.z, a.w, b.x, b.y, b.z, b.w};
#pragma unroll
        for (int q = 0; q < 8; q++) zs[tid * 8 + q] = cosf(xs[q]) * cosf(__ldg(ry + q));
    }
    __syncthreads();

    const int w = tid >> 5, lane = tid & 31;
#pragma unroll 1
    for (int fi = 0; fi < 8; fi++) {
        const int f0 = fi * 256 + lane * 8;
        float4 wq[8][2];
#pragma unroll
        for (int q = 0; q < 8; q++) {
            wq[q][0] = *reinterpret_cast<const float4*>(w1t + q * kF + f0);
            wq[q][1] = *reinterpret_cast<const float4*>(w1t + q * kF + f0 + 4);
        }
        const float4 bq0 = *reinterpret_cast<const float4*>(b1s + f0);
        const float4 bq1 = *reinterpret_cast<const float4*>(b1s + f0 + 4);
#pragma unroll
        for (int rr = 0; rr < 8; rr++) {
            const int rl = w * 8 + rr;
            const float4 z0 = *reinterpret_cast<const float4*>(zs + rl * 8);
            const float4 z1 = *reinterpret_cast<const float4*>(zs + rl * 8 + 4);
            const float zq[8] = {z0.x, z0.y, z0.z, z0.w, z1.x, z1.y, z1.z, z1.w};
            float h[8] = {bq0.x, bq0.y, bq0.z, bq0.w, bq1.x, bq1.y, bq1.z, bq1.w};
#pragma unroll
            for (int q = 0; q < 8; q++) {
                const float z = zq[q];
                h[0] = fmaf(z, wq[q][0].x, h[0]); h[1] = fmaf(z, wq[q][0].y, h[1]);
                h[2] = fmaf(z, wq[q][0].z, h[2]); h[3] = fmaf(z, wq[q][0].w, h[3]);
                h[4] = fmaf(z, wq[q][1].x, h[4]); h[5] = fmaf(z, wq[q][1].y, h[5]);
                h[6] = fmaf(z, wq[q][1].z, h[6]); h[7] = fmaf(z, wq[q][1].w, h[7]);
            }
            __half2 p0 = __floats2half2_rn(fmaxf(h[0], 0.f), fmaxf(h[1], 0.f));
            __half2 p1 = __floats2half2_rn(fmaxf(h[2], 0.f), fmaxf(h[3], 0.f));
            __half2 p2 = __floats2half2_rn(fmaxf(h[4], 0.f), fmaxf(h[5], 0.f));
            __half2 p3 = __floats2half2_rn(fmaxf(h[6], 0.f), fmaxf(h[7], 0.f));
            uint4 pk;
            pk.x = *reinterpret_cast<uint32_t*>(&p0);
            pk.y = *reinterpret_cast<uint32_t*>(&p1);
            pk.z = *reinterpret_cast<uint32_t*>(&p2);
            pk.w = *reinterpret_cast<uint32_t*>(&p3);
            const size_t row = (size_t)blockIdx.x * AROWS + rl;
            *reinterpret_cast<uint4*>(g_act + row * kF + f0) = pk;
        }
    }
}

// ---------------- kernel 3: GEMM out = act @ w2^T + b2, 2 CTAs/SM ----------------
__global__ void __launch_bounds__(GTHR, 2)
ffq_gemm(const float* __restrict__ b2, float* __restrict__ out) {
    extern __shared__ char smem[];
    const uint32_t sb = smem_u32(smem);
    const int tid  = threadIdx.x;
    const int lane = tid & 31;
    const int wid  = tid >> 5;
    const int wm   = wid >> 2;            // 0..1 (m)
    const int wn   = wid & 3;             // 0..3 (n)
    const int m0   = (blockIdx.x >> 2) * BM;
    const int n0   = (blockIdx.x & 3) * BN;

    auto fill = [&](int st, int c) {
        const uint32_t As = sb + st * STAGE_BYTES;
        const uint32_t Bs = As + BM * 128;
        const int k0 = c * BK;
#pragma unroll
        for (int i = 0; i < 4; i++) {          // A: 1024 x 16B segs
            const int s = tid + i * GTHR;
            const int r = s >> 3, j = s & 7;
            cp_async16(As + sw128((uint32_t)(r * 128 + j * 16)),
                       g_act + ((size_t)(m0 + r) * kF + k0 + j * 8));
        }
#pragma unroll
        for (int i = 0; i < 4; i++) {          // B: 1024 x 16B segs
            const int s = tid + i * GTHR;
            const int n = s >> 3, j = s & 7;
            cp_async16(Bs + sw128((uint32_t)(n * 128 + j * 16)),
                       g_w2h + ((size_t)(n0 + n) * kF + k0 + j * 8));
        }
    };

    fill(0, 0); cp_commit();
    fill(1, 1); cp_commit();

    float acc[4][4][4];
#pragma unroll
    for (int mi = 0; mi < 4; mi++)
#pragma unroll
        for (int ni = 0; ni < 4; ni++)
#pragma unroll
            for (int j = 0; j < 4; j++) acc[mi][ni][j] = 0.f;

#pragma unroll 1
    for (int c = 0; c < NCHUNK; c++) {
        cp_wait1();
        __syncthreads();
        if (c + 2 < NCHUNK) { fill((c + 2) % STAGES, c + 2); }
        cp_commit();

        const uint32_t Ab = sb + (c % STAGES) * STAGE_BYTES;
        const uint32_t Bb = Ab + BM * 128;
#pragma unroll
        for (int kc = 0; kc < 4; kc++) {
            uint32_t a[4][4];
#pragma unroll
            for (int mi = 0; mi < 4; mi++) {
                uint32_t row = wm * 64 + mi * 16 + (lane & 15);
                uint32_t col = kc * 32 + (lane >> 4) * 16;
                ldsm4(a[mi], Ab + sw128(row * 128 + col));
            }
            uint32_t b[2][4];
#pragma unroll
            for (int np = 0; np < 2; np++) {
                uint32_t row = wn * 32 + np * 16 + ((lane >> 4) & 1) * 8 + (lane & 7);
                uint32_t col = kc * 32 + ((lane >> 3) & 1) * 16;
                ldsm4(b[np], Bb + sw128(row * 128 + col));
            }
#pragma unroll
            for (int mi = 0; mi < 4; mi++)
#pragma unroll
                for (int ni = 0; ni < 4; ni++) {
                    uint32_t bf[2] = {b[ni >> 1][(ni & 1) * 2], b[ni >> 1][(ni & 1) * 2 + 1]};
                    mma16816(acc[mi][ni], a[mi], bf);
                }
        }
    }

    // epilogue
#pragma unroll
    for (int ni = 0; ni < 4; ni++) {
        const int colp = n0 + wn * 32 + ni * 8 + (lane & 3) * 2;
        const float2 bv = __ldg(reinterpret_cast<const float2*>(b2 + colp));
#pragma unroll
        for (int mi = 0; mi < 4; mi++) {
            const int row0 = m0 + wm * 64 + mi * 16 + (lane >> 2);
            float2 v0 = make_float2(acc[mi][ni][0] + bv.x, acc[mi][ni][1] + bv.y);
            float2 v1 = make_float2(acc[mi][ni][2] + bv.x, acc[mi][ni][3] + bv.y);
            *reinterpret_cast<float2*>(out + (size_t)row0 * kE + colp) = v0;
            *reinterpret_cast<float2*>(out + (size_t)(row0 + 8) * kE + colp) = v1;
        }
    }
}

// ---------------- launch ----------------
extern "C" void kernel_launch(void* const* d_in, const int* in_sizes, int n_in,
                              void* d_out, int out_size) {
    (void)in_sizes; (void)n_in; (void)out_size;
    const float* x  = (const float*)d_in[0];
    const float* ry = (const float*)d_in[1];
    const float* w1 = (const float*)d_in[2];
    const float* b1 = (const float*)d_in[3];
    const float* w2 = (const float*)d_in[4];
    const float* b2 = (const float*)d_in[5];
    float* out = (float*)d_out;

    ffq_convert_w2<<<1024, 256>>>(w2);

    cudaFuncSetAttribute(ffq_act, cudaFuncAttributeMaxDynamicSharedMemorySize, ASMEM);
    ffq_act<<<kRows / AROWS, ATHR, ASMEM>>>(x, ry, w1, b1);

    cudaFuncSetAttribute(ffq_gemm, cudaFuncAttributeMaxDynamicSharedMemorySize, GSMEM);
    ffq_gemm<<<(kRows / BM) * (kE / BN), GTHR, GSMEM>>>(b2, out);
}